// round 2
// baseline (speedup 1.0000x reference)
#include <cuda_runtime.h>
#include <math.h>

#define SEQ   4096
#define DIM   512
#define NHEAD 8
#define HD    64
#define TDIM  1536   // 3*DIM

// Scratch (no allocation allowed)
__device__ float g_qkv[SEQ * TDIM];   // 25 MB
__device__ float g_attn[SEQ * DIM];   // 8 MB

// ---------------------------------------------------------------------------
// NT GEMM: C[M,N] = A[M,K] @ B[N,K]^T + bias[N]
// A row-major lda=K, B row-major ldb=K (both K-contiguous), C row-major.
// 64x64x16 tiles, 256 threads, 4x4 micro-tile per thread.
// ---------------------------------------------------------------------------
template<int M, int N, int K>
__global__ __launch_bounds__(256) void gemm_nt_bias(
    const float* __restrict__ A, const float* __restrict__ B,
    const float* __restrict__ bias, float* __restrict__ C)
{
    constexpr int BK = 16;
    constexpr int P  = 68;              // padded stride (floats), 68*4B is 16B-mult
    __shared__ float As[BK][P];         // As[k][m]
    __shared__ float Bs[BK][P];         // Bs[k][n]

    const int tid = threadIdx.x;
    const int tx = tid % 16;            // n-group
    const int ty = tid / 16;            // m-group
    const int m0 = blockIdx.y * 64;
    const int n0 = blockIdx.x * 64;

    const int lr = tid / 4;             // 0..63 tile row for loading
    const int lk = (tid % 4) * 4;       // k offset (float4)

    float acc[4][4] = {};

    for (int k0 = 0; k0 < K; k0 += BK) {
        float4 a = *(const float4*)&A[(size_t)(m0 + lr) * K + k0 + lk];
        float4 b = *(const float4*)&B[(size_t)(n0 + lr) * K + k0 + lk];
        __syncthreads();   // previous iteration's reads done
        As[lk + 0][lr] = a.x; As[lk + 1][lr] = a.y;
        As[lk + 2][lr] = a.z; As[lk + 3][lr] = a.w;
        Bs[lk + 0][lr] = b.x; Bs[lk + 1][lr] = b.y;
        Bs[lk + 2][lr] = b.z; Bs[lk + 3][lr] = b.w;
        __syncthreads();

        #pragma unroll
        for (int k = 0; k < BK; k++) {
            float4 av = *(const float4*)&As[k][ty * 4];
            float4 bv = *(const float4*)&Bs[k][tx * 4];
            acc[0][0] += av.x * bv.x; acc[0][1] += av.x * bv.y;
            acc[0][2] += av.x * bv.z; acc[0][3] += av.x * bv.w;
            acc[1][0] += av.y * bv.x; acc[1][1] += av.y * bv.y;
            acc[1][2] += av.y * bv.z; acc[1][3] += av.y * bv.w;
            acc[2][0] += av.z * bv.x; acc[2][1] += av.z * bv.y;
            acc[2][2] += av.z * bv.z; acc[2][3] += av.z * bv.w;
            acc[3][0] += av.w * bv.x; acc[3][1] += av.w * bv.y;
            acc[3][2] += av.w * bv.z; acc[3][3] += av.w * bv.w;
        }
    }

    const float4 bv = *(const float4*)&bias[n0 + tx * 4];
    #pragma unroll
    for (int i = 0; i < 4; i++) {
        float4 o;
        o.x = acc[i][0] + bv.x; o.y = acc[i][1] + bv.y;
        o.z = acc[i][2] + bv.z; o.w = acc[i][3] + bv.w;
        *(float4*)&C[(size_t)(m0 + ty * 4 + i) * N + n0 + tx * 4] = o;
    }
}

// ---------------------------------------------------------------------------
// Flash attention: one CTA per (64-query tile, head). fp32.
// qkv layout: [S, 1536] with q|k|v at col offsets 0|512|1024, head h at +h*64.
// Shared tiles (dynamic): QsT[d][q], KsT[d][kk], Vs[kk][d], Ps[q][kk], stride 68.
// ---------------------------------------------------------------------------
#define FA_P 68
#define FA_SMEM (4 * 64 * FA_P * sizeof(float))

__global__ __launch_bounds__(256) void flash_attn(
    const float* __restrict__ qkv, float* __restrict__ out)
{
    extern __shared__ float sm[];
    float* QsT = sm;
    float* KsT = sm + 64 * FA_P;
    float* Vs  = sm + 2 * 64 * FA_P;
    float* Ps  = sm + 3 * 64 * FA_P;

    const int h  = blockIdx.y;
    const int q0 = blockIdx.x * 64;
    const int tid = threadIdx.x;
    const int tx = tid % 16;
    const int ty = tid / 16;
    const int lr = tid / 16;            // load row base (0..15), step 16
    const int ld = (tid % 16) * 4;      // load col (float4)
    const float scale = 0.125f;         // 1/sqrt(64)

    // Load Q tile transposed & pre-scaled: QsT[d][q]
    #pragma unroll
    for (int rr = 0; rr < 4; rr++) {
        int r = lr + rr * 16;
        float4 v = *(const float4*)&qkv[(size_t)(q0 + r) * TDIM + h * HD + ld];
        QsT[(ld + 0) * FA_P + r] = v.x * scale;
        QsT[(ld + 1) * FA_P + r] = v.y * scale;
        QsT[(ld + 2) * FA_P + r] = v.z * scale;
        QsT[(ld + 3) * FA_P + r] = v.w * scale;
    }

    float m[4], l[4], o[4][4];
    #pragma unroll
    for (int i = 0; i < 4; i++) {
        m[i] = -INFINITY; l[i] = 0.f;
        o[i][0] = o[i][1] = o[i][2] = o[i][3] = 0.f;
    }

    for (int kb = 0; kb < SEQ; kb += 64) {
        __syncthreads();   // previous PV / loads done
        // K tile transposed, V tile direct
        #pragma unroll
        for (int rr = 0; rr < 4; rr++) {
            int r = lr + rr * 16;
            float4 kv = *(const float4*)&qkv[(size_t)(kb + r) * TDIM + DIM + h * HD + ld];
            KsT[(ld + 0) * FA_P + r] = kv.x;
            KsT[(ld + 1) * FA_P + r] = kv.y;
            KsT[(ld + 2) * FA_P + r] = kv.z;
            KsT[(ld + 3) * FA_P + r] = kv.w;
            float4 vv = *(const float4*)&qkv[(size_t)(kb + r) * TDIM + 2 * DIM + h * HD + ld];
            *(float4*)&Vs[r * FA_P + ld] = vv;
        }
        __syncthreads();

        // S = (Q*scale) K^T  : 4x4 per thread
        float s[4][4] = {};
        #pragma unroll
        for (int d = 0; d < 64; d++) {
            float4 av = *(const float4*)&QsT[d * FA_P + ty * 4];
            float4 bv = *(const float4*)&KsT[d * FA_P + tx * 4];
            s[0][0] += av.x * bv.x; s[0][1] += av.x * bv.y;
            s[0][2] += av.x * bv.z; s[0][3] += av.x * bv.w;
            s[1][0] += av.y * bv.x; s[1][1] += av.y * bv.y;
            s[1][2] += av.y * bv.z; s[1][3] += av.y * bv.w;
            s[2][0] += av.z * bv.x; s[2][1] += av.z * bv.y;
            s[2][2] += av.z * bv.z; s[2][3] += av.z * bv.w;
            s[3][0] += av.w * bv.x; s[3][1] += av.w * bv.y;
            s[3][2] += av.w * bv.z; s[3][3] += av.w * bv.w;
        }

        // Online softmax. Row r = ty*4+i is owned by the 16 lanes of a
        // half-warp (ty constant across lanes 0-15 / 16-31) -> xor masks 8..1.
        #pragma unroll
        for (int i = 0; i < 4; i++) {
            float lm = fmaxf(fmaxf(s[i][0], s[i][1]), fmaxf(s[i][2], s[i][3]));
            #pragma unroll
            for (int mask = 8; mask >= 1; mask >>= 1)
                lm = fmaxf(lm, __shfl_xor_sync(0xffffffffu, lm, mask));
            float mn = fmaxf(m[i], lm);
            float corr = __expf(m[i] - mn);
            m[i] = mn;
            float rs = 0.f;
            #pragma unroll
            for (int j = 0; j < 4; j++) { s[i][j] = __expf(s[i][j] - mn); rs += s[i][j]; }
            #pragma unroll
            for (int mask = 8; mask >= 1; mask >>= 1)
                rs += __shfl_xor_sync(0xffffffffu, rs, mask);
            l[i] = l[i] * corr + rs;
            o[i][0] *= corr; o[i][1] *= corr; o[i][2] *= corr; o[i][3] *= corr;
            *(float4*)&Ps[(ty * 4 + i) * FA_P + tx * 4] =
                make_float4(s[i][0], s[i][1], s[i][2], s[i][3]);
        }
        __syncthreads();

        // O += P V
        #pragma unroll
        for (int k = 0; k < 64; k++) {
            float4 v = *(const float4*)&Vs[k * FA_P + tx * 4];
            float p0 = Ps[(ty * 4 + 0) * FA_P + k];
            float p1 = Ps[(ty * 4 + 1) * FA_P + k];
            float p2 = Ps[(ty * 4 + 2) * FA_P + k];
            float p3 = Ps[(ty * 4 + 3) * FA_P + k];
            o[0][0] += p0 * v.x; o[0][1] += p0 * v.y; o[0][2] += p0 * v.z; o[0][3] += p0 * v.w;
            o[1][0] += p1 * v.x; o[1][1] += p1 * v.y; o[1][2] += p1 * v.z; o[1][3] += p1 * v.w;
            o[2][0] += p2 * v.x; o[2][1] += p2 * v.y; o[2][2] += p2 * v.z; o[2][3] += p2 * v.w;
            o[3][0] += p3 * v.x; o[3][1] += p3 * v.y; o[3][2] += p3 * v.z; o[3][3] += p3 * v.w;
        }
    }

    // Normalize + write [S, D] (head-interleaved) for the output projection
    #pragma unroll
    for (int i = 0; i < 4; i++) {
        float inv = 1.f / l[i];
        float4 r = make_float4(o[i][0] * inv, o[i][1] * inv, o[i][2] * inv, o[i][3] * inv);
        *(float4*)&out[(size_t)(q0 + ty * 4 + i) * DIM + h * HD + tx * 4] = r;
    }
}

// ---------------------------------------------------------------------------
extern "C" void kernel_launch(void* const* d_in, const int* in_sizes, int n_in,
                              void* d_out, int out_size)
{
    const float* query = (const float*)d_in[0];
    const float* w_in  = (const float*)d_in[1];   // [1536, 512]
    const float* b_in  = (const float*)d_in[2];   // [1536]
    const float* w_out = (const float*)d_in[3];   // [512, 512]
    const float* b_out = (const float*)d_in[4];   // [512]
    float* out = (float*)d_out;

    float *qkv, *attn;
    cudaGetSymbolAddress((void**)&qkv,  g_qkv);
    cudaGetSymbolAddress((void**)&attn, g_attn);

    // 1) QKV projection: [4096,1536] = Q @ Win^T + b
    gemm_nt_bias<SEQ, TDIM, DIM><<<dim3(TDIM / 64, SEQ / 64), 256>>>(query, w_in, b_in, qkv);

    // 2) Flash attention per head
    cudaFuncSetAttribute(flash_attn, cudaFuncAttributeMaxDynamicSharedMemorySize, FA_SMEM);
    flash_attn<<<dim3(SEQ / 64, NHEAD), 256, FA_SMEM>>>(qkv, attn);

    // 3) Output projection: [4096,512] = attn @ Wout^T + b
    gemm_nt_bias<SEQ, DIM, DIM><<<dim3(DIM / 64, SEQ / 64), 256>>>(attn, w_out, b_out, out);
}